// round 9
// baseline (speedup 1.0000x reference)
#include <cuda_runtime.h>

#define THREADS 256
#define PTS 8            // points per block (warp = point)
#define XS 20            // x word stride (16 words + 4 pad): bank 20g+t4 conflict-free
#define HS 36            // h word stride (32 words + 4): bank 4g+t4 conflict-free
#define WS 72            // weight word stride: bank 8t4+g conflict-free
#define CTR_S 72

// ---- shared memory (32-bit words), phase-unioned ----
// union: phase1 xhi[256][20]@0, xlo@5120 ; phase2 hhi[256][36]@0, hlo@9216
#define OFF_XHI  0
#define OFF_XLO  5120
#define OFF_HHI  0
#define OFF_HLO  9216
#define OFF_W2H  18432
#define OFF_W2L  (OFF_W2H + 16 * WS)
#define OFF_W3H  (OFF_W2L + 16 * WS)
#define OFF_W3L  (OFF_W3H + 32 * WS)
#define OFF_W1   (OFF_W3L + 32 * WS)
#define OFF_B1   (OFF_W1 + 192)
#define OFF_G1   (OFF_B1 + 32)
#define OFF_BE1  (OFF_G1 + 32)
#define OFF_B2   (OFF_BE1 + 32)
#define OFF_G2   (OFF_B2 + 64)
#define OFF_BE2  (OFF_G2 + 64)
#define OFF_B3   (OFF_BE2 + 64)
#define OFF_OB   (OFF_B3 + 64)
#define OFF_LG   (OFF_OB + 128)
#define OFF_LB   (OFF_LG + 128)
#define OFF_CTR  (OFF_LB + 128)
#define SMEM_FLOATS (OFF_CTR + PTS * CTR_S)

__device__ __forceinline__ float wsum(float v) {
  #pragma unroll
  for (int o = 16; o > 0; o >>= 1) v += __shfl_xor_sync(0xffffffffu, v, o);
  return v;
}

// pack two floats to bf16x2: e0 -> low half (even k), e1 -> high half (odd k)
__device__ __forceinline__ unsigned pack_bf16(float e0, float e1) {
  unsigned r; asm("cvt.rn.bf16x2.f32 %0, %1, %2;" : "=r"(r) : "f"(e1), "f"(e0));
  return r;
}
// split (e0,e1) into bf16 hi word + bf16 lo (residual) word
__device__ __forceinline__ void split_pair(float e0, float e1, unsigned &hi, unsigned &lo) {
  hi = pack_bf16(e0, e1);
  const float h0 = __uint_as_float(hi << 16);
  const float h1 = __uint_as_float(hi & 0xffff0000u);
  lo = pack_bf16(e0 - h0, e1 - h1);
}

__device__ __forceinline__ void mma16(float c[4], const unsigned a[4], const unsigned b[2]) {
  asm("mma.sync.aligned.m16n8k16.row.col.f32.bf16.bf16.f32 "
      "{%0,%1,%2,%3}, {%4,%5,%6,%7}, {%8,%9}, {%0,%1,%2,%3};"
      : "+f"(c[0]), "+f"(c[1]), "+f"(c[2]), "+f"(c[3])
      : "r"(a[0]), "r"(a[1]), "r"(a[2]), "r"(a[3]), "r"(b[0]), "r"(b[1]));
}

// C[warp's 32 rows][64] += A @ B, fp32 accuracy via bf16 3-term split.
// A words: sA*[row*as + j] (word j packs k=2j,2j+1). B words: sB*[j*WS + n].
template<int KT>   // KT = K/16 k-tiles
__device__ __forceinline__ void gemm_bf16(const unsigned* __restrict__ sAhi,
                                          const unsigned* __restrict__ sAlo, int as,
                                          const unsigned* __restrict__ sBhi,
                                          const unsigned* __restrict__ sBlo,
                                          int mb, int g, int t4, float C[2][8][4])
{
  #pragma unroll
  for (int kt = 0; kt < KT; ++kt) {
    const int j0 = 8 * kt + t4;
    unsigned ahi[2][4], alo[2][4];
    #pragma unroll
    for (int mt = 0; mt < 2; ++mt) {
      const int r = mb + 16 * mt + g;
      ahi[mt][0] = sAhi[r * as + j0];           alo[mt][0] = sAlo[r * as + j0];
      ahi[mt][1] = sAhi[(r + 8) * as + j0];     alo[mt][1] = sAlo[(r + 8) * as + j0];
      ahi[mt][2] = sAhi[r * as + j0 + 4];       alo[mt][2] = sAlo[r * as + j0 + 4];
      ahi[mt][3] = sAhi[(r + 8) * as + j0 + 4]; alo[mt][3] = sAlo[(r + 8) * as + j0 + 4];
    }
    #pragma unroll
    for (int nt = 0; nt < 8; ++nt) {
      const int n = 8 * nt + g;
      unsigned bhi[2], blo[2];
      bhi[0] = sBhi[j0 * WS + n]; bhi[1] = sBhi[(j0 + 4) * WS + n];
      blo[0] = sBlo[j0 * WS + n]; blo[1] = sBlo[(j0 + 4) * WS + n];
      #pragma unroll
      for (int mt = 0; mt < 2; ++mt) {
        mma16(C[mt][nt], ahi[mt], bhi);
        mma16(C[mt][nt], ahi[mt], blo);
        mma16(C[mt][nt], alo[mt], bhi);
      }
    }
  }
}

extern "C" __global__ void __launch_bounds__(THREADS, 2)
so3conv_kernel(const float* __restrict__ pts, const float* __restrict__ nbr,
               const float* __restrict__ w1, const float* __restrict__ b1,
               const float* __restrict__ g1, const float* __restrict__ be1,
               const float* __restrict__ w2, const float* __restrict__ b2,
               const float* __restrict__ g2, const float* __restrict__ be2,
               const float* __restrict__ w3, const float* __restrict__ b3,
               const float* __restrict__ ow, const float* __restrict__ ob,
               const float* __restrict__ lg, const float* __restrict__ lb,
               float* __restrict__ out)
{
  extern __shared__ float s[];
  unsigned* su = reinterpret_cast<unsigned*>(s);
  const int tid = threadIdx.x;

  // ---- stage weights, pre-split to bf16 hi/lo packed words ----
  for (int i = tid; i < 16 * 64; i += THREADS) {
    const int j = i >> 6, n = i & 63;
    unsigned hi, lo;
    split_pair(w2[j * 128 + n], w2[j * 128 + 64 + n], hi, lo);
    su[OFF_W2H + j * WS + n] = hi; su[OFF_W2L + j * WS + n] = lo;
  }
  for (int i = tid; i < 32 * 64; i += THREADS) {
    const int j = i >> 6, n = i & 63;
    unsigned hi, lo;
    split_pair(w3[j * 128 + n], w3[j * 128 + 64 + n], hi, lo);
    su[OFF_W3H + j * WS + n] = hi; su[OFF_W3L + j * WS + n] = lo;
  }
  for (int i = tid; i < 192; i += THREADS) s[OFF_W1 + i] = w1[i];
  if (tid < 32) { s[OFF_B1 + tid] = b1[tid]; s[OFF_G1 + tid] = g1[tid]; s[OFF_BE1 + tid] = be1[tid]; }
  if (tid < 64) { s[OFF_B2 + tid] = b2[tid]; s[OFF_G2 + tid] = g2[tid]; s[OFF_BE2 + tid] = be2[tid]; s[OFF_B3 + tid] = b3[tid]; }
  if (tid < 128) { s[OFF_OB + tid] = ob[tid]; s[OFF_LG + tid] = lg[tid]; s[OFF_LB + tid] = lb[tid]; }

  const int warp = tid >> 5;
  const int lane = tid & 31;
  const int g  = lane >> 2;
  const int t4 = lane & 3;
  const int mb = warp * 32;
  const int point = blockIdx.x * PTS + warp;

  // ================= rifeat (warp = point, lane = neighbor) =================
  const float px = pts[point * 3 + 0];
  const float py = pts[point * 3 + 1];
  const float pz = pts[point * 3 + 2];
  const float* nb = nbr + (size_t)point * 96 + lane * 3;
  const float nx = nb[0], ny = nb[1], nz = nb[2];

  const float mx = wsum(nx) * 0.03125f;
  const float my = wsum(ny) * 0.03125f;
  const float mz = wsum(nz) * 0.03125f;

  const float l1x = mx - nx, l1y = my - ny, l1z = mz - nz;
  const float l2x = nx - px, l2y = ny - py, l2z = nz - pz;
  const float l3x = px - mx, l3y = py - my, l3z = pz - mz;
  const float n1 = sqrtf(l1x * l1x + l1y * l1y + l1z * l1z);
  const float n2 = sqrtf(l2x * l2x + l2y * l2y + l2z * l2z);
  const float n3 = sqrtf(l3x * l3x + l3y * l3y + l3z * l3z);
  const float d12 = l1x * l2x + l1y * l2y + l1z * l2z;
  const float d23 = l2x * l3x + l2y * l3y + l2z * l3z;
  const float d31 = l3x * l1x + l3y * l1y + l3z * l1z;
  float f[6];
  f[0] = n1; f[1] = n2; f[2] = n3;
  f[3] = d12 / (n1 * n2 + 1e-7f);
  f[4] = d23 / (n2 * n3 + 1e-7f);
  f[5] = d31 / (n3 * n1 + 1e-7f);

  __syncthreads();   // staging complete

  // ========== layer 1: [6]@[6,32] + b1, LN(32) lane-local, relu -> split x ==========
  {
    float x[32];
    #pragma unroll
    for (int j = 0; j < 32; ++j) x[j] = s[OFF_B1 + j];
    #pragma unroll
    for (int i = 0; i < 6; ++i) {
      const float a = f[i];
      #pragma unroll
      for (int j = 0; j < 32; ++j) x[j] += a * s[OFF_W1 + i * 32 + j];
    }
    float sm = 0.f;
    #pragma unroll
    for (int j = 0; j < 32; ++j) sm += x[j];
    const float mu = sm * (1.f / 32.f);
    float vs = 0.f;
    #pragma unroll
    for (int j = 0; j < 32; ++j) { const float d = x[j] - mu; vs += d * d; }
    const float inv = rsqrtf(vs * (1.f / 32.f) + 1e-5f);
    #pragma unroll
    for (int j = 0; j < 32; ++j)
      x[j] = fmaxf(0.f, (x[j] - mu) * inv * s[OFF_G1 + j] + s[OFF_BE1 + j]);
    #pragma unroll
    for (int q = 0; q < 16; ++q) {
      unsigned hi, lo;
      split_pair(x[2 * q], x[2 * q + 1], hi, lo);
      su[OFF_XHI + tid * XS + q] = hi;
      su[OFF_XLO + tid * XS + q] = lo;
    }
  }
  __syncthreads();

  // ===== layer 2: bf16 tensor GEMM [32 x 64], K=32 (2 k-tiles) =====
  float C[2][8][4];
  #pragma unroll
  for (int nt = 0; nt < 8; ++nt) {
    const float2 b = *reinterpret_cast<const float2*>(&s[OFF_B2 + 8 * nt + 2 * t4]);
    C[0][nt][0] = b.x; C[0][nt][1] = b.y; C[0][nt][2] = b.x; C[0][nt][3] = b.y;
    C[1][nt][0] = b.x; C[1][nt][1] = b.y; C[1][nt][2] = b.x; C[1][nt][3] = b.y;
  }
  gemm_bf16<2>(su + OFF_XHI, su + OFF_XLO, XS, su + OFF_W2H, su + OFF_W2L, mb, g, t4, C);

  // ---- LN(64) + relu fully in registers (quad shuffles) ----
  {
    float mu[4], inv[4];
    float sm[4] = {0.f, 0.f, 0.f, 0.f};
    #pragma unroll
    for (int nt = 0; nt < 8; ++nt) {
      sm[0] += C[0][nt][0] + C[0][nt][1];
      sm[1] += C[0][nt][2] + C[0][nt][3];
      sm[2] += C[1][nt][0] + C[1][nt][1];
      sm[3] += C[1][nt][2] + C[1][nt][3];
    }
    #pragma unroll
    for (int r = 0; r < 4; ++r) {
      sm[r] += __shfl_xor_sync(0xffffffffu, sm[r], 1);
      sm[r] += __shfl_xor_sync(0xffffffffu, sm[r], 2);
      mu[r] = sm[r] * (1.f / 64.f);
    }
    float vs[4] = {0.f, 0.f, 0.f, 0.f};
    #pragma unroll
    for (int nt = 0; nt < 8; ++nt) {
      float d;
      d = C[0][nt][0] - mu[0]; vs[0] += d * d;
      d = C[0][nt][1] - mu[0]; vs[0] += d * d;
      d = C[0][nt][2] - mu[1]; vs[1] += d * d;
      d = C[0][nt][3] - mu[1]; vs[1] += d * d;
      d = C[1][nt][0] - mu[2]; vs[2] += d * d;
      d = C[1][nt][1] - mu[2]; vs[2] += d * d;
      d = C[1][nt][2] - mu[3]; vs[3] += d * d;
      d = C[1][nt][3] - mu[3]; vs[3] += d * d;
    }
    #pragma unroll
    for (int r = 0; r < 4; ++r) {
      vs[r] += __shfl_xor_sync(0xffffffffu, vs[r], 1);
      vs[r] += __shfl_xor_sync(0xffffffffu, vs[r], 2);
      inv[r] = rsqrtf(vs[r] * (1.f / 64.f) + 1e-5f);
    }
    #pragma unroll
    for (int nt = 0; nt < 8; ++nt) {
      const float2 gg = *reinterpret_cast<const float2*>(&s[OFF_G2 + 8 * nt + 2 * t4]);
      const float2 bb = *reinterpret_cast<const float2*>(&s[OFF_BE2 + 8 * nt + 2 * t4]);
      C[0][nt][0] = fmaxf(0.f, (C[0][nt][0] - mu[0]) * inv[0] * gg.x + bb.x);
      C[0][nt][1] = fmaxf(0.f, (C[0][nt][1] - mu[0]) * inv[0] * gg.y + bb.y);
      C[0][nt][2] = fmaxf(0.f, (C[0][nt][2] - mu[1]) * inv[1] * gg.x + bb.x);
      C[0][nt][3] = fmaxf(0.f, (C[0][nt][3] - mu[1]) * inv[1] * gg.y + bb.y);
      C[1][nt][0] = fmaxf(0.f, (C[1][nt][0] - mu[2]) * inv[2] * gg.x + bb.x);
      C[1][nt][1] = fmaxf(0.f, (C[1][nt][1] - mu[2]) * inv[2] * gg.y + bb.y);
      C[1][nt][2] = fmaxf(0.f, (C[1][nt][2] - mu[3]) * inv[3] * gg.x + bb.x);
      C[1][nt][3] = fmaxf(0.f, (C[1][nt][3] - mu[3]) * inv[3] * gg.y + bb.y);
    }
  }
  __syncthreads();   // retire all x reads before h overwrites the union region

  // store h as pre-split bf16 hi/lo words: word (4nt+t4) packs cols (8nt+2t4, +1)
  #pragma unroll
  for (int mt = 0; mt < 2; ++mt) {
    const int r = mb + 16 * mt + g;
    #pragma unroll
    for (int nt = 0; nt < 8; ++nt) {
      const int w = 4 * nt + t4;
      unsigned hi, lo;
      split_pair(C[mt][nt][0], C[mt][nt][1], hi, lo);
      su[OFF_HHI + r * HS + w] = hi; su[OFF_HLO + r * HS + w] = lo;
      split_pair(C[mt][nt][2], C[mt][nt][3], hi, lo);
      su[OFF_HHI + (r + 8) * HS + w] = hi; su[OFF_HLO + (r + 8) * HS + w] = lo;
    }
  }
  __syncthreads();

  // ===== layer 3: bf16 tensor GEMM K=64 (4 k-tiles), then max over 32 rows =====
  #pragma unroll
  for (int nt = 0; nt < 8; ++nt) {
    const float2 b = *reinterpret_cast<const float2*>(&s[OFF_B3 + 8 * nt + 2 * t4]);
    C[0][nt][0] = b.x; C[0][nt][1] = b.y; C[0][nt][2] = b.x; C[0][nt][3] = b.y;
    C[1][nt][0] = b.x; C[1][nt][1] = b.y; C[1][nt][2] = b.x; C[1][nt][3] = b.y;
  }
  gemm_bf16<4>(su + OFF_HHI, su + OFF_HLO, HS, su + OFF_W3H, su + OFF_W3L, mb, g, t4, C);

  {
    float m0[8], m1[8];
    #pragma unroll
    for (int nt = 0; nt < 8; ++nt) {
      m0[nt] = fmaxf(fmaxf(C[0][nt][0], C[0][nt][2]), fmaxf(C[1][nt][0], C[1][nt][2]));
      m1[nt] = fmaxf(fmaxf(C[0][nt][1], C[0][nt][3]), fmaxf(C[1][nt][1], C[1][nt][3]));
    }
    #pragma unroll
    for (int off = 4; off <= 16; off <<= 1) {
      #pragma unroll
      for (int nt = 0; nt < 8; ++nt) {
        m0[nt] = fmaxf(m0[nt], __shfl_xor_sync(0xffffffffu, m0[nt], off));
        m1[nt] = fmaxf(m1[nt], __shfl_xor_sync(0xffffffffu, m1[nt], off));
      }
    }
    if (lane < 4) {   // g==0: t4 covers all column groups
      #pragma unroll
      for (int nt = 0; nt < 8; ++nt)
        *reinterpret_cast<float2*>(&s[OFF_CTR + warp * CTR_S + 8 * nt + 2 * t4]) =
            make_float2(m0[nt], m1[nt]);
    }
  }
  __syncthreads();

  // ==== layer 4: warp = point; lane = 4 cols; ow streamed from L2; LN(128) ====
  {
    const float* ctr = &s[OFF_CTR + warp * CTR_S];
    float4 a = *reinterpret_cast<const float4*>(&s[OFF_OB + 4 * lane]);
    #pragma unroll
    for (int i = 0; i < 64; ++i) {
      const float c = ctr[i];
      const float4 w = *reinterpret_cast<const float4*>(&ow[i * 128 + 4 * lane]);
      a.x += c * w.x; a.y += c * w.y; a.z += c * w.z; a.w += c * w.w;
    }
    const float sm = wsum(a.x + a.y + a.z + a.w);
    const float mu = sm * (1.f / 128.f);
    const float dx = a.x - mu, dy = a.y - mu, dz = a.z - mu, dw = a.w - mu;
    const float vs = wsum(dx * dx + dy * dy + dz * dz + dw * dw);
    const float inv = rsqrtf(vs * (1.f / 128.f) + 1e-5f);
    const float4 gv = *reinterpret_cast<const float4*>(&s[OFF_LG + 4 * lane]);
    const float4 bv = *reinterpret_cast<const float4*>(&s[OFF_LB + 4 * lane]);
    float4 o;
    o.x = dx * inv * gv.x + bv.x;
    o.y = dy * inv * gv.y + bv.y;
    o.z = dz * inv * gv.z + bv.z;
    o.w = dw * inv * gv.w + bv.w;
    *reinterpret_cast<float4*>(&out[(size_t)point * 128 + 4 * lane]) = o;
  }
}

extern "C" void kernel_launch(void* const* d_in, const int* in_sizes, int n_in,
                              void* d_out, int out_size) {
  const float* pts = (const float*)d_in[0];
  const float* nbr = (const float*)d_in[1];
  const float* w1  = (const float*)d_in[2];
  const float* b1  = (const float*)d_in[3];
  const float* g1  = (const float*)d_in[4];
  const float* be1 = (const float*)d_in[5];
  const float* w2  = (const float*)d_in[6];
  const float* b2  = (const float*)d_in[7];
  const float* g2  = (const float*)d_in[8];
  const float* be2 = (const float*)d_in[9];
  const float* w3  = (const float*)d_in[10];
  const float* b3  = (const float*)d_in[11];
  const float* ow  = (const float*)d_in[12];
  const float* ob  = (const float*)d_in[13];
  const float* lg  = (const float*)d_in[14];
  const float* lb  = (const float*)d_in[15];

  const int P = in_sizes[1] / 96;          // B*N points
  const int grid = P / PTS;                // 4096

  cudaFuncSetAttribute(so3conv_kernel,
                       cudaFuncAttributeMaxDynamicSharedMemorySize,
                       (int)(SMEM_FLOATS * sizeof(float)));
  so3conv_kernel<<<grid, THREADS, SMEM_FLOATS * sizeof(float)>>>(
      pts, nbr, w1, b1, g1, be1, w2, b2, g2, be2, w3, b3,
      ow, ob, lg, lb, (float*)d_out);
}